// round 2
// baseline (speedup 1.0000x reference)
#include <cuda_runtime.h>
#include <stdint.h>

// UniformShardedEmbeddingBags: weights [E,T,D] fp32, indices [B,T,L] int32 -> out [B,T,D] fp32
// E=200000, T=16, D=64, B=4096, L=20
#define EB_E 200000
#define EB_T 16
#define EB_D 64
#define EB_L 20
#define EB_B 4096

// 16 threads per bag; each thread accumulates one float4 (4 of the 64 dims).
// Row gather = 16 lanes x 16B = two perfectly coalesced 128B lines.
// L=20 unrolled loads are independent -> high MLP to cover DRAM latency.
__global__ __launch_bounds__(256) void embbag_kernel(
    const float* __restrict__ weights,
    const int* __restrict__ indices,
    float* __restrict__ out)
{
    int gt = blockIdx.x * blockDim.x + threadIdx.x;
    int bag = gt >> 4;          // b*T + t
    int lane = gt & 15;         // float4 slot within the 64-dim row
    if (bag >= EB_B * EB_T) return;

    int t = bag & (EB_T - 1);   // T==16

    const int* ip = indices + (size_t)bag * EB_L;  // [B,T,L] contiguous: bag-major

    float4 acc = make_float4(0.f, 0.f, 0.f, 0.f);

#pragma unroll
    for (int l = 0; l < EB_L; ++l) {
        int e = __ldg(ip + l);
        const float4* row = reinterpret_cast<const float4*>(
            weights + ((size_t)e * EB_T + t) * EB_D);
        float4 v = __ldg(row + lane);
        acc.x += v.x; acc.y += v.y; acc.z += v.z; acc.w += v.w;
    }

    reinterpret_cast<float4*>(out)[(size_t)bag * 16 + lane] = acc;
}

extern "C" void kernel_launch(void* const* d_in, const int* in_sizes, int n_in,
                              void* d_out, int out_size)
{
    // Defensive input selection by element count:
    // weights = 200000*16*64 = 204,800,000 ; indices = 4096*16*20 = 1,310,720
    const float* weights = (const float*)d_in[0];
    const int*   indices = (const int*)d_in[1];
    if (n_in >= 2 && in_sizes[0] < in_sizes[1]) {
        weights = (const float*)d_in[1];
        indices = (const int*)d_in[0];
    }
    float* out = (float*)d_out;

    const int total_threads = EB_B * EB_T * 16;   // 1,048,576
    const int block = 256;
    const int grid = (total_threads + block - 1) / block;  // 4096
    embbag_kernel<<<grid, block>>>(weights, indices, out);
}

// round 3
// speedup vs baseline: 1.0786x; 1.0786x over previous
#include <cuda_runtime.h>
#include <stdint.h>

// UniformShardedEmbeddingBags: weights [E,T,D] fp32, indices [B,T,L] int32 -> out [B,T,D] fp32
// E=200000, T=16, D=64, B=4096, L=20
#define EB_E 200000
#define EB_T 16
#define EB_D 64
#define EB_L 20
#define EB_B 4096

// 16 threads per bag, one float4 (16B) per thread -> row gather is 16 lanes x 16B
// = two coalesced 128B lines.
//
// Grid ordering is TABLE-MAJOR: blocks [t*256, (t+1)*256) process all 4096 bags
// of table t. A single table's distinct-row working set is ~17MB (<< 126MB L2),
// and the concurrent-block window spans only ~2-3 tables, so the ~1.24x
// per-table index reuse is captured in L2 instead of re-fetched from DRAM.
//
// __launch_bounds__(256, 8) caps regs at 32 -> full 2048-thread occupancy.
__global__ __launch_bounds__(256, 8) void embbag_kernel(
    const float* __restrict__ weights,
    const int* __restrict__ indices,
    float* __restrict__ out)
{
    // 256 blocks per table, 16 bags per block.
    const int t = blockIdx.x >> 8;                       // table 0..15
    const int b = ((blockIdx.x & 255) << 4) + (threadIdx.x >> 4);  // batch 0..4095
    const int lane = threadIdx.x & 15;                   // float4 slot in 64-dim row

    const int bag = b * EB_T + t;                        // [B,T] bag id
    const int* ip = indices + (size_t)bag * EB_L;

    const float4* wbase = reinterpret_cast<const float4*>(weights) + lane;

    float4 acc = make_float4(0.f, 0.f, 0.f, 0.f);

#pragma unroll
    for (int l = 0; l < EB_L; ++l) {
        int e = __ldg(ip + l);
        float4 v = __ldg(wbase + ((size_t)e * EB_T + t) * (EB_D / 4));
        acc.x += v.x; acc.y += v.y; acc.z += v.z; acc.w += v.w;
    }

    reinterpret_cast<float4*>(out)[(size_t)bag * 16 + lane] = acc;
}

extern "C" void kernel_launch(void* const* d_in, const int* in_sizes, int n_in,
                              void* d_out, int out_size)
{
    // weights = 204,800,000 elems ; indices = 1,310,720 elems
    const float* weights = (const float*)d_in[0];
    const int*   indices = (const int*)d_in[1];
    if (n_in >= 2 && in_sizes[0] < in_sizes[1]) {
        weights = (const float*)d_in[1];
        indices = (const int*)d_in[0];
    }
    float* out = (float*)d_out;

    const int block = 256;
    const int grid = EB_T * 256;   // 4096 blocks, table-major
    embbag_kernel<<<grid, block>>>(weights, indices, out);
}